// round 16
// baseline (speedup 1.0000x reference)
#include <cuda_runtime.h>
#include <cstdint>

#define NN 10000
#define HID 16
#define LAB 7
#define KC 32             // k per chunk
#define RPB 64            // rows per block
#define FP 36             // feat smem pitch (floats)
#define WP 24             // W smem pitch (floats)
#define NCHT 313          // ceil(10000/32)
#define KSPLIT 15
#define NUNITS (157 * KSPLIT)   // 2355 -> 3.98 rounds on 592 slots
#define PGRID 592         // 4 blocks/SM, single persistent wave
#define LASTCH 312        // the only partial chunk (k 9984..9999)
#define MAXE 320000

__device__ int g_is64;
__device__ unsigned g_ctr;
__device__ __align__(16) float g_deg_src[NN];
__device__ __align__(16) float g_deg_dst[NN];
__device__ __align__(16) int g_src[MAXE];
__device__ __align__(16) int g_dst[MAXE];
__device__ __align__(16) unsigned g_w1t[NN * HID];   // W1 pre-rounded to tf32 (rna)
__device__ __align__(16) float g_h[NN * HID];        // (features @ W1) * norm_src
__device__ __align__(16) float g_agg1[NN * HID];
__device__ __align__(16) float g_h2[NN * 8];
__device__ __align__(16) float g_agg2[NN * 8];

// ---------- helpers ----------
__device__ __forceinline__ void redg_v4(float* p, float4 v) {
    unsigned long long gp;
    asm("cvta.to.global.u64 %0, %1;" : "=l"(gp) : "l"(p));
    asm volatile("red.global.add.v4.f32 [%0], {%1, %2, %3, %4};"
                 ::"l"(gp), "f"(v.x), "f"(v.y), "f"(v.z), "f"(v.w) : "memory");
}
__device__ __forceinline__ void redg_v2(float* p, float a, float b) {
    unsigned long long gp;
    asm("cvta.to.global.u64 %0, %1;" : "=l"(gp) : "l"(p));
    asm volatile("red.global.add.v2.f32 [%0], {%1, %2};"
                 ::"l"(gp), "f"(a), "f"(b) : "memory");
}
__device__ __forceinline__ void redg_f32(float* p, float v) {
    unsigned long long gp;
    asm("cvta.to.global.u64 %0, %1;" : "=l"(gp) : "l"(p));
    asm volatile("red.global.add.f32 [%0], %1;" ::"l"(gp), "f"(v) : "memory");
}
__device__ __forceinline__ void cp16(unsigned smem_dst, const void* gsrc, int sz) {
    asm volatile("cp.async.cg.shared.global [%0], [%1], 16, %2;"
                 ::"r"(smem_dst), "l"(gsrc), "r"(sz));
}
__device__ __forceinline__ unsigned tf32r(float f) {
    unsigned r;
    asm("cvt.rna.tf32.f32 %0, %1;" : "=r"(r) : "f"(f));
    return r;
}
__device__ __forceinline__ void ldm4(unsigned* a, unsigned addr) {
    asm volatile("ldmatrix.sync.aligned.m8n8.x4.shared.b16 {%0,%1,%2,%3}, [%4];"
                 : "=r"(a[0]), "=r"(a[1]), "=r"(a[2]), "=r"(a[3]) : "r"(addr));
}
__device__ __forceinline__ void mma8(float* d, const unsigned* a, unsigned b0,
                                     unsigned b1) {
    asm volatile(
        "mma.sync.aligned.m16n8k8.row.col.f32.tf32.tf32.f32 "
        "{%0,%1,%2,%3}, {%4,%5,%6,%7}, {%8,%9}, {%0,%1,%2,%3};"
        : "+f"(d[0]), "+f"(d[1]), "+f"(d[2]), "+f"(d[3])
        : "r"(a[0]), "r"(a[1]), "r"(a[2]), "r"(a[3]), "r"(b0), "r"(b1));
}
__device__ __forceinline__ int clampn(int v) { return min(max(v, 0), NN - 1); }
__device__ __forceinline__ float nrm(float deg) { return rsqrtf(fmaxf(deg, 1.f)); }

// ---------- K0: detect dtype + zero scratch + pre-round W1 to tf32 ----------
__global__ void k_init(const int* __restrict__ src, const float* __restrict__ W1) {
    int i = blockIdx.x * blockDim.x + threadIdx.x;
    if (i == 0) {
        int all_odd_zero = 1;
        for (int t = 1; t < 256; t += 2)
            if (src[t] != 0) { all_odd_zero = 0; break; }
        g_is64 = all_odd_zero;
        g_ctr = 0u;
    }
    int stride = gridDim.x * blockDim.x;
    for (int t = i; t < NN; t += stride) { g_deg_src[t] = 0.f; g_deg_dst[t] = 0.f; }
    for (int t = i; t < NN * HID; t += stride) {
        g_h[t] = 0.f;
        g_agg1[t] = 0.f;
        g_w1t[t] = tf32r(W1[t]);
    }
    for (int t = i; t < NN * 8; t += stride) g_agg2[t] = 0.f;
}

// ---------- K1: degrees + pack indices (2 edges/thread) ----------
__global__ void k_deg(const void* __restrict__ src, const void* __restrict__ dst, int nE) {
    int p = blockIdx.x * blockDim.x + threadIdx.x;
    int e0 = 2 * p, e1 = e0 + 1;
    if (e0 >= nE) return;
    int is64 = g_is64;
    int s0, s1, d0, d1;
    if (is64) {
        longlong2 sv = *(const longlong2*)((const long long*)src + e0);
        longlong2 dv = *(const longlong2*)((const long long*)dst + e0);
        s0 = clampn((int)sv.x); s1 = clampn((int)sv.y);
        d0 = clampn((int)dv.x); d1 = clampn((int)dv.y);
    } else {
        int2 sv = *(const int2*)((const int*)src + e0);
        int2 dv = *(const int2*)((const int*)dst + e0);
        s0 = clampn(sv.x); s1 = clampn(sv.y);
        d0 = clampn(dv.x); d1 = clampn(dv.y);
    }
    int ok1 = (e1 < nE);
    g_src[e0] = s0;
    g_dst[e0] = d0;
    redg_f32(&g_deg_src[s0], 1.f);
    redg_f32(&g_deg_dst[d0], 1.f);
    if (ok1) {
        g_src[e1] = s1;
        g_dst[e1] = d1;
        redg_f32(&g_deg_src[s1], 1.f);
        redg_f32(&g_deg_dst[d1], 1.f);
    }
}

// ---------- K2: persistent tf32 tensor-core GEMM (epilogue scales by norm_src) ----------
__global__ void __launch_bounds__(256, 4)
k_gemm1(const float* __restrict__ feat) {
    __shared__ __align__(16) float sF[3][RPB * FP];     // 27648 B
    __shared__ __align__(16) unsigned sW[3][KC * WP];   // 9216 B
    __shared__ __align__(16) float sD[4][256];          // 4096 B
    __shared__ int s_unit;

    const int tid = threadIdx.x;
    const int w = tid >> 5;
    const int lane = tid & 31;
    const int mt = w & 3;
    const int kh = w >> 2;
    const int g_ = lane >> 2;
    const int t_ = lane & 3;
    const int lrow = mt * 16 + ((lane >> 3) & 1) * 8 + (lane & 7);
    const int lcol = ((lane >> 4) & 1) * 4 + kh * 16;

    unsigned fAddr[3];
#pragma unroll
    for (int b = 0; b < 3; b++)
        fAddr[b] = (unsigned)__cvta_generic_to_shared(&sF[b][lrow * FP + lcol]);

    int wOff[2][2];
#pragma unroll
    for (int kt = 0; kt < 2; kt++)
#pragma unroll
        for (int nt = 0; nt < 2; nt++)
            wOff[kt][nt] = (kh * 16 + kt * 8 + t_) * WP + nt * 8 + g_;

    const int srow0 = tid >> 3;            // 0..31
    const int fq = tid & 7;
    unsigned fDst0[3], fDst1[3], wDst[3];
#pragma unroll
    for (int b = 0; b < 3; b++) {
        fDst0[b] = (unsigned)__cvta_generic_to_shared(&sF[b][srow0 * FP + fq * 4]);
        fDst1[b] = (unsigned)__cvta_generic_to_shared(&sF[b][(srow0 + 32) * FP + fq * 4]);
        wDst[b] = (unsigned)__cvta_generic_to_shared(&sW[b][(tid >> 2) * WP + (tid & 3) * 4]);
    }
    const int wRow = tid >> 2;
    const unsigned* wBase = g_w1t + (size_t)wRow * HID + (tid & 3) * 4;

    for (;;) {
        if (tid == 0) s_unit = (int)atomicAdd(&g_ctr, 1u);
        __syncthreads();
        const int u = s_unit;
        if (u >= NUNITS) return;

        const int rowBase = (u / KSPLIT) * RPB;
        const int ks = u % KSPLIT;
        const int ch0 = (ks * NCHT) / KSPLIT;
        const int nch = ((ks + 1) * NCHT) / KSPLIT - ch0;

        const int gr0 = rowBase + srow0, gr1 = gr0 + 32;
        const int sz0 = (gr0 < NN) ? 16 : 0, sz1 = (gr1 < NN) ? 16 : 0;
        const float* fr0 = feat + (size_t)min(gr0, NN - 1) * NN;
        const float* fr1 = feat + (size_t)min(gr1, NN - 1) * NN;

        const float* pf0 = fr0 + ch0 * KC + 4 * fq;
        const float* pf1 = fr1 + ch0 * KC + 4 * fq;
        const unsigned* pw = wBase + (size_t)ch0 * KC * HID;
        int chunkIdx = ch0;

        auto issue = [&](int c) {
            if (c < nch) {
                const int b = c % 3;
                if (chunkIdx != LASTCH) {
                    cp16(fDst0[b], pf0, sz0);
                    cp16(fDst1[b], pf1, sz1);
                    if (tid < 128) cp16(wDst[b], pw, 16);
                } else {
                    const int gc = LASTCH * KC + 4 * fq;
                    const int szc = (gc < NN) ? 16 : 0;
                    const float* q0 = fr0 + min(gc, NN - 4);
                    const float* q1 = fr1 + min(gc, NN - 4);
                    cp16(fDst0[b], q0, min(sz0, szc));
                    cp16(fDst1[b], q1, min(sz1, szc));
                    if (tid < 128) {
                        int gk = LASTCH * KC + wRow;
                        cp16(wDst[b], g_w1t + (size_t)min(gk, NN - 1) * HID + (tid & 3) * 4,
                             (gk < NN) ? 16 : 0);
                    }
                }
                pf0 += KC; pf1 += KC; pw += (size_t)KC * HID; chunkIdx++;
            }
            asm volatile("cp.async.commit_group;" ::: "memory");
        };

        float d[2][4];
#pragma unroll
        for (int nt = 0; nt < 2; nt++)
#pragma unroll
            for (int i = 0; i < 4; i++) d[nt][i] = 0.f;

        issue(0); issue(1);

        for (int c = 0; c < nch; c++) {
            const int b = c % 3;
            asm volatile("cp.async.wait_group 1;" ::: "memory");
            __syncthreads();

            const unsigned* wb = sW[b];
#pragma unroll
            for (int kt = 0; kt < 2; kt++) {
                unsigned a[4];
                ldm4(a, fAddr[b] + kt * 32);
#pragma unroll
                for (int i = 0; i < 4; i++) a[i] = tf32r(__uint_as_float(a[i]));
#pragma unroll
                for (int nt = 0; nt < 2; nt++) {
                    unsigned b0 = wb[wOff[kt][nt]];
                    unsigned b1 = wb[wOff[kt][nt] + 4 * WP];
                    mma8(d[nt], a, b0, b1);
                }
            }
            issue(c + 2);
        }

        // pairwise cross-warp reduce: warps 4-7 stash, warps 0-3 combine,
        // scale by norm_src (linear in the K-partials), RED to g_h.
        if (w >= 4) {
#pragma unroll
            for (int nt = 0; nt < 2; nt++) {
                sD[mt][g_ * 16 + nt * 8 + 2 * t_] = d[nt][0];
                sD[mt][g_ * 16 + nt * 8 + 2 * t_ + 1] = d[nt][1];
                sD[mt][(g_ + 8) * 16 + nt * 8 + 2 * t_] = d[nt][2];
                sD[mt][(g_ + 8) * 16 + nt * 8 + 2 * t_ + 1] = d[nt][3];
            }
        }
        __syncthreads();
        if (w < 4) {
            const int or0 = rowBase + mt * 16 + g_;
            const int or1 = or0 + 8;
            const float f0 = nrm(g_deg_src[min(or0, NN - 1)]);
            const float f1 = nrm(g_deg_src[min(or1, NN - 1)]);
#pragma unroll
            for (int nt = 0; nt < 2; nt++) {
                float v0 = f0 * (d[nt][0] + sD[mt][g_ * 16 + nt * 8 + 2 * t_]);
                float v1 = f0 * (d[nt][1] + sD[mt][g_ * 16 + nt * 8 + 2 * t_ + 1]);
                float v2 = f1 * (d[nt][2] + sD[mt][(g_ + 8) * 16 + nt * 8 + 2 * t_]);
                float v3 = f1 * (d[nt][3] + sD[mt][(g_ + 8) * 16 + nt * 8 + 2 * t_ + 1]);
                if (or0 < NN) redg_v2(&g_h[(size_t)or0 * HID + nt * 8 + 2 * t_], v0, v1);
                if (or1 < NN) redg_v2(&g_h[(size_t)or1 * HID + nt * 8 + 2 * t_], v2, v3);
            }
        }
    }
}

// ---------- K3: scatter layer 1 — 4 lanes/edge, 2 edges/thread ----------
__global__ void k_scatter1(int nE) {
    int gid = blockIdx.x * blockDim.x + threadIdx.x;
    int p = gid >> 2;          // edge-pair index
    int q = gid & 3;           // float4 quad within row
    int e0 = 2 * p, e1 = e0 + 1;
    if (e0 >= nE) return;
    int2 ss = *(const int2*)(g_src + e0);
    int2 dd = *(const int2*)(g_dst + e0);
    int ok1 = (e1 < nE);
    float4 v0 = ((const float4*)(g_h + (size_t)ss.x * HID))[q];
    float4 v1;
    if (ok1) v1 = ((const float4*)(g_h + (size_t)ss.y * HID))[q];
    redg_v4(g_agg1 + (size_t)dd.x * HID + 4 * q, v0);
    if (ok1) redg_v4(g_agg1 + (size_t)dd.y * HID + 4 * q, v1);
}

// ---------- K4: h1 = relu(agg1*norm_dst + b1); h2 = (h1*norm_src) @ W2 ----------
__global__ void k_layer2(const float* __restrict__ b1, const float* __restrict__ W2) {
    int n = blockIdx.x * blockDim.x + threadIdx.x;
    if (n >= NN) return;
    float nd = nrm(g_deg_dst[n]), ns = nrm(g_deg_src[n]);
    float h1[HID];
    const float4* ap = (const float4*)(g_agg1 + (size_t)n * HID);
#pragma unroll
    for (int q = 0; q < 4; q++) {
        float4 v = ap[q];
        h1[4 * q + 0] = fmaxf(fmaf(v.x, nd, __ldg(&b1[4 * q + 0])), 0.f);
        h1[4 * q + 1] = fmaxf(fmaf(v.y, nd, __ldg(&b1[4 * q + 1])), 0.f);
        h1[4 * q + 2] = fmaxf(fmaf(v.z, nd, __ldg(&b1[4 * q + 2])), 0.f);
        h1[4 * q + 3] = fmaxf(fmaf(v.w, nd, __ldg(&b1[4 * q + 3])), 0.f);
    }
    float o[LAB];
#pragma unroll
    for (int j = 0; j < LAB; j++) o[j] = 0.f;
#pragma unroll
    for (int k = 0; k < HID; k++) {
        float hv = h1[k];
#pragma unroll
        for (int j = 0; j < LAB; j++) o[j] = fmaf(hv, __ldg(&W2[k * LAB + j]), o[j]);
    }
#pragma unroll
    for (int j = 0; j < LAB; j++) g_h2[n * 8 + j] = ns * o[j];
    g_h2[n * 8 + 7] = 0.f;
}

// ---------- K5: scatter layer 2 — 2 lanes/edge, 2 edges/thread ----------
__global__ void k_scatter2(int nE) {
    int gid = blockIdx.x * blockDim.x + threadIdx.x;
    int p = gid >> 1;
    int q = gid & 1;
    int e0 = 2 * p, e1 = e0 + 1;
    if (e0 >= nE) return;
    int2 ss = *(const int2*)(g_src + e0);
    int2 dd = *(const int2*)(g_dst + e0);
    int ok1 = (e1 < nE);
    float4 v0 = ((const float4*)(g_h2 + (size_t)ss.x * 8))[q];
    float4 v1;
    if (ok1) v1 = ((const float4*)(g_h2 + (size_t)ss.y * 8))[q];
    redg_v4(g_agg2 + (size_t)dd.x * 8 + 4 * q, v0);
    if (ok1) redg_v4(g_agg2 + (size_t)dd.y * 8 + 4 * q, v1);
}

// ---------- K6: finalize ----------
__global__ void k_final(const float* __restrict__ b2, float* __restrict__ out) {
    int i = blockIdx.x * blockDim.x + threadIdx.x;
    if (i >= NN * LAB) return;
    int n = i / LAB, j = i - n * LAB;
    out[i] = fmaf(g_agg2[n * 8 + j], nrm(g_deg_dst[n]), __ldg(&b2[j]));
}

extern "C" void kernel_launch(void* const* d_in, const int* in_sizes, int n_in,
                              void* d_out, int out_size) {
    const float* feat = (const float*)d_in[0];
    const void* src = d_in[1];
    const void* dst = d_in[2];
    const float* W1 = (const float*)d_in[3];
    const float* b1 = (const float*)d_in[4];
    const float* W2 = (const float*)d_in[5];
    const float* b2 = (const float*)d_in[6];
    int nE = in_sizes[1];
    if (nE > MAXE) nE = MAXE;
    float* out = (float*)d_out;

    int ebd = ((nE + 1) / 2 + 255) / 256;           // k_deg: 2 edges/thread
    int eb1 = (((nE + 1) / 2) * 4 + 255) / 256;     // scatter1 threads
    int eb2 = (((nE + 1) / 2) * 2 + 255) / 256;     // scatter2 threads

    k_init<<<256, 256>>>((const int*)src, W1);
    k_deg<<<ebd, 256>>>(src, dst, nE);
    k_gemm1<<<PGRID, 256>>>(feat);
    k_scatter1<<<eb1, 256>>>(nE);
    k_layer2<<<(NN + 255) / 256, 256>>>(b1, W2);
    k_scatter2<<<eb2, 256>>>(nE);
    k_final<<<(NN * LAB + 255) / 256, 256>>>(b2, out);
}